// round 1
// baseline (speedup 1.0000x reference)
#include <cuda_runtime.h>
#include <math.h>

#define S_     2048
#define HID_   2048
#define H_     16
#define HKV_   4
#define D_     128
#define GROUPS_ 4
#define SCALE_ 0.08838834764831845f   // 128^-0.5

#define PAD 129   // smem row pitch (floats) for conflict-free column reads

// ---------------- scratch (no cudaMalloc allowed) ----------------
__device__ float g_q   [S_*H_*D_];      // 16 MB
__device__ float g_k   [S_*HKV_*D_];    //  4 MB
__device__ float g_v   [S_*HKV_*D_];    //  4 MB
__device__ float g_g   [S_*HKV_];       // 32 KB
__device__ float g_gc  [HKV_*S_];       // 32 KB  (cumsum of log-sigmoid gates, per kv head)
__device__ float g_attn[S_*H_*D_];      // 16 MB

// ---------------- generic tiled SGEMM: C = A(MxK) @ B(KxN), row-major ----
// 64x64 tile, 256 threads (16x16), 4x4 micro-tile, K-step 16.
// Requires M % 64 == 0 and K % 16 == 0 (true for all calls here). N guarded.
__global__ void sgemm64(const float* __restrict__ A, const float* __restrict__ B,
                        float* __restrict__ C, int M, int N, int K) {
    __shared__ float As[16][64];
    __shared__ float Bs[16][64];
    const int tx = threadIdx.x, ty = threadIdx.y;
    const int tid = ty * 16 + tx;
    const int bm = blockIdx.y * 64, bn = blockIdx.x * 64;

    float acc[4][4] = {};

    for (int kt = 0; kt < K; kt += 16) {
        // A tile -> As[kk][m]
        {
            const int kk = tid & 15;
            const int m0 = tid >> 4;
            #pragma unroll
            for (int r = 0; r < 4; r++) {
                const int m = m0 + r * 16;
                As[kk][m] = A[(bm + m) * K + kt + kk];
            }
        }
        // B tile -> Bs[kk][n]
        {
            const int n  = tid & 63;
            const int k0 = tid >> 6;
            const int gn = bn + n;
            #pragma unroll
            for (int r = 0; r < 4; r++) {
                const int kk = k0 + r * 4;
                Bs[kk][n] = (gn < N) ? B[(kt + kk) * N + gn] : 0.f;
            }
        }
        __syncthreads();
        #pragma unroll
        for (int kk = 0; kk < 16; kk++) {
            float a[4], b[4];
            #pragma unroll
            for (int i = 0; i < 4; i++) a[i] = As[kk][ty * 4 + i];
            #pragma unroll
            for (int u = 0; u < 4; u++) b[u] = Bs[kk][tx + 16 * u];
            #pragma unroll
            for (int i = 0; i < 4; i++)
                #pragma unroll
                for (int u = 0; u < 4; u++)
                    acc[i][u] = fmaf(a[i], b[u], acc[i][u]);
        }
        __syncthreads();
    }

    #pragma unroll
    for (int i = 0; i < 4; i++) {
        const int gm = bm + ty * 4 + i;
        #pragma unroll
        for (int u = 0; u < 4; u++) {
            const int gn = bn + tx + 16 * u;
            if (gn < N) C[gm * N + gn] = acc[i][u];
        }
    }
}

// ---------------- RoPE (in place) ----------------
// x: (S, nheads*128). cos/sin: (S, 128) with cos[d] == cos[d+64].
__global__ void rope_kernel(float* __restrict__ x, const float* __restrict__ cosb,
                            const float* __restrict__ sinb, int nheads) {
    const int idx = blockIdx.x * blockDim.x + threadIdx.x;
    const int total = S_ * nheads * 64;
    if (idx >= total) return;
    const int d = idx % 64;
    const int h = (idx / 64) % nheads;
    const int s = idx / (64 * nheads);
    const float c  = cosb[s * 128 + d];
    const float sn = sinb[s * 128 + d];
    float* row = x + (size_t)s * nheads * 128 + h * 128;
    const float x0 = row[d], x1 = row[d + 64];
    row[d]      = x0 * c - x1 * sn;   // x0*cos + (-x1)*sin
    row[d + 64] = x1 * c + x0 * sn;   // x1*cos +   x0 *sin
}

// ---------------- log-sigmoid + serial cumsum per kv head ----------------
__global__ void gcumsum_kernel() {
    const int kv = threadIdx.x;
    if (kv >= HKV_) return;
    float acc = 0.f;
    for (int s = 0; s < S_; s++) {
        const float x = g_g[s * HKV_ + kv];
        // log_sigmoid(x), numerically stable both sides
        const float ls = (x > 0.f) ? -log1pf(expf(-x)) : x - log1pf(expf(x));
        acc += ls;
        g_gc[kv * S_ + s] = acc;
    }
}

// ---------------- causal power attention ----------------
// grid: (S/64, H). block: (16,16). Each CTA: one head, 64 query rows.
// O[r][c] accumulated in registers (4 rows x 8 cols per thread).
__global__ void attn_kernel() {
    extern __shared__ float sm[];
    float* Qs  = sm;                 // 64*PAD
    float* Ks  = Qs + 64 * PAD;      // 64*PAD
    float* Vs  = Ks + 64 * PAD;      // 64*PAD
    float* Ss  = Vs + 64 * PAD;      // 64*65
    float* Gq  = Ss + 64 * 65;       // 64
    float* Gk  = Gq + 64;            // 64
    float* den = Gk + 64;            // 64

    const int qb = blockIdx.x;
    const int h  = blockIdx.y;
    const int kv = h / GROUPS_;
    const int tx = threadIdx.x, ty = threadIdx.y;
    const int tid = ty * 16 + tx;

    // load Q tile, Gq; zero den
    for (int e = tid; e < 64 * 128; e += 256) {
        const int r = e >> 7, d = e & 127;
        Qs[r * PAD + d] = g_q[(size_t)(qb * 64 + r) * (H_ * D_) + h * D_ + d];
    }
    if (tid < 64) {
        Gq[tid]  = g_gc[kv * S_ + qb * 64 + tid];
        den[tid] = 0.f;
    }
    __syncthreads();

    float gq[4];
    #pragma unroll
    for (int i = 0; i < 4; i++) gq[i] = Gq[ty * 4 + i];

    float o[4][8] = {};

    for (int kb = 0; kb <= qb; kb++) {
        __syncthreads();   // previous iteration done reading Ks/Vs/Ss
        for (int e = tid; e < 64 * 128; e += 256) {
            const int r = e >> 7, d = e & 127;
            const int gr = kb * 64 + r;
            Ks[r * PAD + d] = g_k[(size_t)gr * (HKV_ * D_) + kv * D_ + d];
            Vs[r * PAD + d] = g_v[(size_t)gr * (HKV_ * D_) + kv * D_ + d];
        }
        if (tid < 64) Gk[tid] = g_gc[kv * S_ + kb * 64 + tid];
        __syncthreads();

        // S = (Q K^T * scale)^2 * exp(Gq - Gk), causal masked
        float s[4][4] = {};
        #pragma unroll 4
        for (int d = 0; d < 128; d++) {
            float a[4], b[4];
            #pragma unroll
            for (int i = 0; i < 4; i++) a[i] = Qs[(ty * 4 + i) * PAD + d];
            #pragma unroll
            for (int u = 0; u < 4; u++) b[u] = Ks[(tx + 16 * u) * PAD + d];
            #pragma unroll
            for (int i = 0; i < 4; i++)
                #pragma unroll
                for (int u = 0; u < 4; u++)
                    s[i][u] = fmaf(a[i], b[u], s[i][u]);
        }
        #pragma unroll
        for (int i = 0; i < 4; i++) {
            const int gi = qb * 64 + ty * 4 + i;
            #pragma unroll
            for (int u = 0; u < 4; u++) {
                const int j  = tx + 16 * u;
                const int gj = kb * 64 + j;
                float val = 0.f;
                if (gj <= gi) {
                    const float t = s[i][u] * SCALE_;
                    val = t * t * __expf(gq[i] - Gk[j]);   // arg <= 0, no overflow
                }
                Ss[(ty * 4 + i) * 65 + j] = val;
            }
        }
        __syncthreads();

        // row sums into den
        if (tid < 64) {
            float rs = 0.f;
            #pragma unroll 8
            for (int j = 0; j < 64; j++) rs += Ss[tid * 65 + j];
            den[tid] += rs;
        }

        // O += S @ V
        #pragma unroll 2
        for (int j = 0; j < 64; j++) {
            float sv[4], vv[8];
            #pragma unroll
            for (int i = 0; i < 4; i++) sv[i] = Ss[(ty * 4 + i) * 65 + j];
            #pragma unroll
            for (int u = 0; u < 8; u++) vv[u] = Vs[j * PAD + tx + 16 * u];
            #pragma unroll
            for (int i = 0; i < 4; i++)
                #pragma unroll
                for (int u = 0; u < 8; u++)
                    o[i][u] = fmaf(sv[i], vv[u], o[i][u]);
        }
    }
    __syncthreads();

    #pragma unroll
    for (int i = 0; i < 4; i++) {
        const float inv = 1.f / fmaxf(den[ty * 4 + i], 1.f);
        const int gi = qb * 64 + ty * 4 + i;
        #pragma unroll
        for (int u = 0; u < 8; u++)
            g_attn[(size_t)gi * (H_ * D_) + h * D_ + tx + 16 * u] = o[i][u] * inv;
    }
}

// ---------------- launch ----------------
extern "C" void kernel_launch(void* const* d_in, const int* in_sizes, int n_in,
                              void* d_out, int out_size) {
    (void)in_sizes; (void)n_in; (void)out_size;
    const float* hs   = (const float*)d_in[0];
    const float* cosb = (const float*)d_in[1];
    const float* sinb = (const float*)d_in[2];
    const float* Wq   = (const float*)d_in[3];
    const float* Wk   = (const float*)d_in[4];
    const float* Wv   = (const float*)d_in[5];
    const float* Wg   = (const float*)d_in[6];
    const float* Wo   = (const float*)d_in[7];
    float* out = (float*)d_out;

    float *q, *k, *v, *g, *attn;
    cudaGetSymbolAddress((void**)&q,    g_q);
    cudaGetSymbolAddress((void**)&k,    g_k);
    cudaGetSymbolAddress((void**)&v,    g_v);
    cudaGetSymbolAddress((void**)&g,    g_g);
    cudaGetSymbolAddress((void**)&attn, g_attn);

    const dim3 blk(16, 16);

    // projections
    sgemm64<<<dim3((H_*D_)  / 64, S_ / 64), blk>>>(hs, Wq, q, S_, H_*D_,   HID_);
    sgemm64<<<dim3((HKV_*D_)/ 64, S_ / 64), blk>>>(hs, Wk, k, S_, HKV_*D_, HID_);
    sgemm64<<<dim3((HKV_*D_)/ 64, S_ / 64), blk>>>(hs, Wv, v, S_, HKV_*D_, HID_);
    sgemm64<<<dim3(1,            S_ / 64), blk>>>(hs, Wg, g, S_, HKV_,    HID_);

    // RoPE
    rope_kernel<<<(S_*H_*64   + 255) / 256, 256>>>(q, cosb, sinb, H_);
    rope_kernel<<<(S_*HKV_*64 + 255) / 256, 256>>>(k, cosb, sinb, HKV_);

    // gate log-sigmoid + cumsum
    gcumsum_kernel<<<1, 32>>>();

    // attention
    const size_t smem = (size_t)(3 * 64 * PAD + 64 * 65 + 3 * 64) * sizeof(float);
    cudaFuncSetAttribute(attn_kernel, cudaFuncAttributeMaxDynamicSharedMemorySize, (int)smem);
    attn_kernel<<<dim3(S_ / 64, H_), blk, smem>>>();

    // output projection
    sgemm64<<<dim3(HID_ / 64, S_ / 64), blk>>>(attn, Wo, out, S_, HID_, H_*D_);
}

// round 2
// speedup vs baseline: 5.8631x; 5.8631x over previous
#include <cuda_runtime.h>
#include <math.h>

#define S_     2048
#define HID_   2048
#define H_     16
#define HKV_   4
#define D_     128
#define GROUPS_ 4
#define SCALE_ 0.08838834764831845f   // 128^-0.5

#define PAD 129     // attn smem row pitch
#define DECAY_CUT (-40.0f)

// ---------------- scratch (no cudaMalloc allowed) ----------------
__device__ float g_q   [S_*H_*D_];
__device__ float g_k   [S_*HKV_*D_];
__device__ float g_v   [S_*HKV_*D_];
__device__ float g_g   [S_*HKV_];
__device__ float g_gc  [HKV_*S_];
__device__ float g_attn[S_*H_*D_];

// ---------------- tf32 helpers ----------------
__device__ __forceinline__ unsigned f2tf(float x) {
    unsigned r; asm("cvt.rna.tf32.f32 %0, %1;" : "=r"(r) : "f"(x)); return r;
}
__device__ __forceinline__ void mma_tf32(float c[4], const unsigned a[4], const unsigned b[2]) {
    asm volatile("mma.sync.aligned.m16n8k8.row.col.f32.tf32.tf32.f32 "
        "{%0,%1,%2,%3},{%4,%5,%6,%7},{%8,%9},{%0,%1,%2,%3};"
        : "+f"(c[0]), "+f"(c[1]), "+f"(c[2]), "+f"(c[3])
        : "r"(a[0]), "r"(a[1]), "r"(a[2]), "r"(a[3]), "r"(b[0]), "r"(b[1]));
}

// ---------------- tf32 tensor-core GEMM ----------------
// C = A(MxK) @ B(KxN), row-major. BM=BN=128, BK=32, 256 threads (8 warps).
// Warp tile 32x64 -> 2x8 m16n8k8 mmas. Double-buffered smem, reg-staged loads.
// Requires M%128==0, N%128==0, K%32==0 (true for all call sites).
#define BM 128
#define BN 128
#define BK 32
#define PA 36    // As pitch (floats): %32==4  -> conflict-free frag loads
#define PB 136   // Bs pitch (floats): %32==8  -> conflict-free frag loads
#define GEMM_SMEM ((2*BM*PA + 2*BK*PB) * 4)   // 71680 bytes

__global__ void __launch_bounds__(256) gemm_tf32(const float* __restrict__ A,
        const float* __restrict__ B, float* __restrict__ C,
        int M, int N, int K) {
    extern __shared__ unsigned smu[];
    unsigned* As = smu;                 // [2][BM][PA]
    unsigned* Bs = smu + 2 * BM * PA;   // [2][BK][PB]

    const int tid  = threadIdx.x;
    const int lane = tid & 31;
    const int warp = tid >> 5;
    const int wm   = (warp & 3) * 32;
    const int wn   = (warp >> 2) * 64;
    const int bm   = blockIdx.y * BM;
    const int bn   = blockIdx.x * BN;
    const int nk   = K / BK;

    // gmem load coordinates (fixed per thread)
    const int arow = tid >> 3;          // + i*32, i=0..3
    const int acol = (tid & 7) * 4;
    const int brow = tid >> 5;          // + i*8
    const int bcol = (tid & 31) * 4;

    float acc[2][8][4];
    #pragma unroll
    for (int mi = 0; mi < 2; mi++)
        #pragma unroll
        for (int ni = 0; ni < 8; ni++)
            #pragma unroll
            for (int r = 0; r < 4; r++) acc[mi][ni][r] = 0.f;

    // prologue: tile 0 straight into stage 0
    {
        const float* Ab = A + (size_t)bm * K;
        const float* Bb = B + bn;
        #pragma unroll
        for (int i = 0; i < 4; i++) {
            const int r = arow + i * 32;
            float4 v = *(const float4*)(Ab + (size_t)r * K + acol);
            uint4 u = make_uint4(f2tf(v.x), f2tf(v.y), f2tf(v.z), f2tf(v.w));
            *(uint4*)(As + r * PA + acol) = u;
        }
        #pragma unroll
        for (int i = 0; i < 4; i++) {
            const int r = brow + i * 8;
            float4 v = *(const float4*)(Bb + (size_t)r * N + bcol);
            uint4 u = make_uint4(f2tf(v.x), f2tf(v.y), f2tf(v.z), f2tf(v.w));
            *(uint4*)(Bs + r * PB + bcol) = u;
        }
    }
    __syncthreads();

    for (int kt = 0; kt < nk; kt++) {
        float4 ra[4], rb[4];
        const bool more = (kt + 1 < nk);
        if (more) {
            const float* Ab = A + (size_t)bm * K + (kt + 1) * BK;
            const float* Bb = B + (size_t)((kt + 1) * BK) * N + bn;
            #pragma unroll
            for (int i = 0; i < 4; i++)
                ra[i] = *(const float4*)(Ab + (size_t)(arow + i * 32) * K + acol);
            #pragma unroll
            for (int i = 0; i < 4; i++)
                rb[i] = *(const float4*)(Bb + (size_t)(brow + i * 8) * N + bcol);
        }

        // compute current stage
        {
            const unsigned* Ab = As + (kt & 1) * BM * PA;
            const unsigned* Bb = Bs + (kt & 1) * BK * PB;
            #pragma unroll
            for (int ks = 0; ks < BK; ks += 8) {
                unsigned af[2][4], bf[8][2];
                #pragma unroll
                for (int mi = 0; mi < 2; mi++) {
                    const int r = wm + mi * 16 + (lane >> 2);
                    const int c = ks + (lane & 3);
                    af[mi][0] = Ab[r * PA + c];
                    af[mi][1] = Ab[(r + 8) * PA + c];
                    af[mi][2] = Ab[r * PA + c + 4];
                    af[mi][3] = Ab[(r + 8) * PA + c + 4];
                }
                #pragma unroll
                for (int ni = 0; ni < 8; ni++) {
                    const int cn = wn + ni * 8 + (lane >> 2);
                    const int rk = ks + (lane & 3);
                    bf[ni][0] = Bb[rk * PB + cn];
                    bf[ni][1] = Bb[(rk + 4) * PB + cn];
                }
                #pragma unroll
                for (int mi = 0; mi < 2; mi++)
                    #pragma unroll
                    for (int ni = 0; ni < 8; ni++)
                        mma_tf32(acc[mi][ni], af[mi], bf[ni]);
            }
        }

        if (more) {
            unsigned* Ad = As + ((kt + 1) & 1) * BM * PA;
            unsigned* Bd = Bs + ((kt + 1) & 1) * BK * PB;
            #pragma unroll
            for (int i = 0; i < 4; i++) {
                uint4 u = make_uint4(f2tf(ra[i].x), f2tf(ra[i].y), f2tf(ra[i].z), f2tf(ra[i].w));
                *(uint4*)(Ad + (arow + i * 32) * PA + acol) = u;
            }
            #pragma unroll
            for (int i = 0; i < 4; i++) {
                uint4 u = make_uint4(f2tf(rb[i].x), f2tf(rb[i].y), f2tf(rb[i].z), f2tf(rb[i].w));
                *(uint4*)(Bd + (brow + i * 8) * PB + bcol) = u;
            }
        }
        __syncthreads();
    }

    // epilogue
    #pragma unroll
    for (int mi = 0; mi < 2; mi++) {
        const int r0 = bm + wm + mi * 16 + (lane >> 2);
        #pragma unroll
        for (int ni = 0; ni < 8; ni++) {
            const int c0 = bn + wn + ni * 8 + 2 * (lane & 3);
            *(float2*)(C + (size_t)r0 * N + c0)       = make_float2(acc[mi][ni][0], acc[mi][ni][1]);
            *(float2*)(C + (size_t)(r0 + 8) * N + c0) = make_float2(acc[mi][ni][2], acc[mi][ni][3]);
        }
    }
}

// ---------------- gate projection: g = hs @ Wg (N=4) ----------------
// one block per s-row (128 threads = 4 warps), warp w computes column w.
__global__ void gate_proj(const float* __restrict__ hs, const float* __restrict__ Wg) {
    const int s = blockIdx.x;
    const int w = threadIdx.x >> 5, l = threadIdx.x & 31;
    const float* row = hs + (size_t)s * HID_;
    float acc = 0.f;
    for (int k = l; k < HID_; k += 32)
        acc = fmaf(row[k], Wg[k * HKV_ + w], acc);
    #pragma unroll
    for (int o = 16; o > 0; o >>= 1)
        acc += __shfl_down_sync(0xffffffffu, acc, o);
    if (l == 0) g_g[s * HKV_ + w] = acc;
}

// ---------------- log-sigmoid + parallel cumsum (one block per kv head) ----
__global__ void gcumsum_kernel() {
    __shared__ float ps[256];
    const int kv = blockIdx.x;
    const int t = threadIdx.x;      // 256 threads, 8 contiguous elems each
    float loc[8]; float s = 0.f;
    #pragma unroll
    for (int i = 0; i < 8; i++) {
        const float x = g_g[(t * 8 + i) * HKV_ + kv];
        const float ls = (x > 0.f) ? -log1pf(__expf(-x)) : x - log1pf(__expf(x));
        loc[i] = ls; s += ls;
    }
    ps[t] = s; __syncthreads();
    for (int o = 1; o < 256; o <<= 1) {
        const float v = (t >= o) ? ps[t - o] : 0.f;
        __syncthreads();
        ps[t] += v;
        __syncthreads();
    }
    float run = (t > 0) ? ps[t - 1] : 0.f;
    #pragma unroll
    for (int i = 0; i < 8; i++) {
        run += loc[i];
        g_gc[kv * S_ + t * 8 + i] = run;
    }
}

// ---------------- RoPE (in place) ----------------
__global__ void rope_kernel(float* __restrict__ x, const float* __restrict__ cosb,
                            const float* __restrict__ sinb, int nheads) {
    const int idx = blockIdx.x * blockDim.x + threadIdx.x;
    const int total = S_ * nheads * 64;
    if (idx >= total) return;
    const int d = idx % 64;
    const int h = (idx / 64) % nheads;
    const int s = idx / (64 * nheads);
    const float c  = cosb[s * 128 + d];
    const float sn = sinb[s * 128 + d];
    float* row = x + (size_t)s * nheads * 128 + h * 128;
    const float x0 = row[d], x1 = row[d + 64];
    row[d]      = x0 * c - x1 * sn;
    row[d + 64] = x1 * c + x0 * sn;
}

// ---------------- causal power attention with exact decay truncation ------
__global__ void attn_kernel() {
    extern __shared__ float sm[];
    float* Qs  = sm;                 // 64*PAD
    float* Ks  = Qs + 64 * PAD;      // 64*PAD
    float* Vs  = Ks + 64 * PAD;      // 64*PAD
    float* Ss  = Vs + 64 * PAD;      // 64*65
    float* Gq  = Ss + 64 * 65;       // 64
    float* Gk  = Gq + 64;            // 64
    float* den = Gk + 64;            // 64

    const int qb = blockIdx.x;
    const int h  = blockIdx.y;
    const int kv = h / GROUPS_;
    const int tx = threadIdx.x, ty = threadIdx.y;
    const int tid = ty * 16 + tx;

    for (int e = tid; e < 64 * 128; e += 256) {
        const int r = e >> 7, d = e & 127;
        Qs[r * PAD + d] = g_q[(size_t)(qb * 64 + r) * (H_ * D_) + h * D_ + d];
    }
    if (tid < 64) {
        Gq[tid]  = g_gc[kv * S_ + qb * 64 + tid];
        den[tid] = 0.f;
    }
    __syncthreads();

    float gq[4];
    #pragma unroll
    for (int i = 0; i < 4; i++) gq[i] = Gq[ty * 4 + i];
    const float Gq0 = Gq[0];   // max G over query tile (G decreasing)

    float o[4][8] = {};

    for (int kb = qb; kb >= 0; kb--) {
        // exact tile-level skip: best-case logdecay below cutoff -> all older
        // blocks are even smaller (G monotone decreasing) -> break.
        if (kb < qb) {
            const float gkLast = g_gc[kv * S_ + kb * 64 + 63];
            if (Gq0 - gkLast < DECAY_CUT) break;
        }
        __syncthreads();   // previous iteration done reading Ks/Vs/Ss
        for (int e = tid; e < 64 * 128; e += 256) {
            const int r = e >> 7, d = e & 127;
            const int gr = kb * 64 + r;
            Ks[r * PAD + d] = g_k[(size_t)gr * (HKV_ * D_) + kv * D_ + d];
            Vs[r * PAD + d] = g_v[(size_t)gr * (HKV_ * D_) + kv * D_ + d];
        }
        if (tid < 64) Gk[tid] = g_gc[kv * S_ + kb * 64 + tid];
        __syncthreads();

        float s[4][4] = {};
        #pragma unroll 4
        for (int d = 0; d < 128; d++) {
            float a[4], b[4];
            #pragma unroll
            for (int i = 0; i < 4; i++) a[i] = Qs[(ty * 4 + i) * PAD + d];
            #pragma unroll
            for (int u = 0; u < 4; u++) b[u] = Ks[(tx + 16 * u) * PAD + d];
            #pragma unroll
            for (int i = 0; i < 4; i++)
                #pragma unroll
                for (int u = 0; u < 4; u++)
                    s[i][u] = fmaf(a[i], b[u], s[i][u]);
        }
        #pragma unroll
        for (int i = 0; i < 4; i++) {
            const int gi = qb * 64 + ty * 4 + i;
            #pragma unroll
            for (int u = 0; u < 4; u++) {
                const int j  = tx + 16 * u;
                const int gj = kb * 64 + j;
                float val = 0.f;
                if (gj <= gi) {
                    const float t = s[i][u] * SCALE_;
                    val = t * t * __expf(gq[i] - Gk[j]);
                }
                Ss[(ty * 4 + i) * 65 + j] = val;
            }
        }
        __syncthreads();

        if (tid < 64) {
            float rs = 0.f;
            #pragma unroll 8
            for (int j = 0; j < 64; j++) rs += Ss[tid * 65 + j];
            den[tid] += rs;
        }

        #pragma unroll 2
        for (int j = 0; j < 64; j++) {
            float sv[4], vv[8];
            #pragma unroll
            for (int i = 0; i < 4; i++) sv[i] = Ss[(ty * 4 + i) * 65 + j];
            #pragma unroll
            for (int u = 0; u < 8; u++) vv[u] = Vs[j * PAD + tx + 16 * u];
            #pragma unroll
            for (int i = 0; i < 4; i++)
                #pragma unroll
                for (int u = 0; u < 8; u++)
                    o[i][u] = fmaf(sv[i], vv[u], o[i][u]);
        }
    }
    __syncthreads();

    #pragma unroll
    for (int i = 0; i < 4; i++) {
        const float inv = 1.f / fmaxf(den[ty * 4 + i], 1.f);
        const int gi = qb * 64 + ty * 4 + i;
        #pragma unroll
        for (int u = 0; u < 8; u++)
            g_attn[(size_t)gi * (H_ * D_) + h * D_ + tx + 16 * u] = o[i][u] * inv;
    }
}

// ---------------- launch ----------------
extern "C" void kernel_launch(void* const* d_in, const int* in_sizes, int n_in,
                              void* d_out, int out_size) {
    (void)in_sizes; (void)n_in; (void)out_size;
    const float* hs   = (const float*)d_in[0];
    const float* cosb = (const float*)d_in[1];
    const float* sinb = (const float*)d_in[2];
    const float* Wq   = (const float*)d_in[3];
    const float* Wk   = (const float*)d_in[4];
    const float* Wv   = (const float*)d_in[5];
    const float* Wg   = (const float*)d_in[6];
    const float* Wo   = (const float*)d_in[7];
    float* out = (float*)d_out;

    float *q, *k, *v, *attn;
    cudaGetSymbolAddress((void**)&q,    g_q);
    cudaGetSymbolAddress((void**)&k,    g_k);
    cudaGetSymbolAddress((void**)&v,    g_v);
    cudaGetSymbolAddress((void**)&attn, g_attn);

    cudaFuncSetAttribute(gemm_tf32, cudaFuncAttributeMaxDynamicSharedMemorySize, GEMM_SMEM);

    // projections (tensor cores)
    gemm_tf32<<<dim3((H_*D_)  / BN, S_ / BM), 256, GEMM_SMEM>>>(hs, Wq, q, S_, H_*D_,   HID_);
    gemm_tf32<<<dim3((HKV_*D_)/ BN, S_ / BM), 256, GEMM_SMEM>>>(hs, Wk, k, S_, HKV_*D_, HID_);
    gemm_tf32<<<dim3((HKV_*D_)/ BN, S_ / BM), 256, GEMM_SMEM>>>(hs, Wv, v, S_, HKV_*D_, HID_);
    gate_proj<<<S_, 128>>>(hs, Wg);

    // RoPE
    rope_kernel<<<(S_*H_*64   + 255) / 256, 256>>>(q, cosb, sinb, H_);
    rope_kernel<<<(S_*HKV_*64 + 255) / 256, 256>>>(k, cosb, sinb, HKV_);

    // gate log-sigmoid + cumsum
    gcumsum_kernel<<<HKV_, 256>>>();

    // attention (decay-truncated)
    const size_t smem = (size_t)(3 * 64 * PAD + 64 * 65 + 3 * 64) * sizeof(float);
    cudaFuncSetAttribute(attn_kernel, cudaFuncAttributeMaxDynamicSharedMemorySize, (int)smem);
    attn_kernel<<<dim3(S_ / 64, H_), dim3(16, 16), smem>>>();

    // output projection (tensor cores)
    gemm_tf32<<<dim3(HID_ / BN, S_ / BM), 256, GEMM_SMEM>>>(attn, Wo, out, S_, HID_, H_*D_);
}

// round 3
// speedup vs baseline: 5.8731x; 1.0017x over previous
#include <cuda_runtime.h>
#include <math.h>

#define S_     2048
#define HID_   2048
#define H_     16
#define HKV_   4
#define D_     128
#define GROUPS_ 4
#define SCALE_ 0.08838834764831845f   // 128^-0.5

#define PAD 129     // attn smem row pitch
#define DECAY_CUT (-40.0f)

// ---------------- scratch (no cudaMalloc allowed) ----------------
__device__ float g_q   [S_*H_*D_];
__device__ float g_k   [S_*HKV_*D_];
__device__ float g_v   [S_*HKV_*D_];
__device__ float g_g   [S_*HKV_];
__device__ float g_gc  [HKV_*S_];
__device__ float g_attn[S_*H_*D_];

// ---------------- tf32 helpers ----------------
__device__ __forceinline__ unsigned f2tf(float x) {
    unsigned r; asm("cvt.rna.tf32.f32 %0, %1;" : "=r"(r) : "f"(x)); return r;
}
__device__ __forceinline__ void mma_tf32(float c[4], const unsigned a[4], const unsigned b[2]) {
    asm volatile("mma.sync.aligned.m16n8k8.row.col.f32.tf32.tf32.f32 "
        "{%0,%1,%2,%3},{%4,%5,%6,%7},{%8,%9},{%0,%1,%2,%3};"
        : "+f"(c[0]), "+f"(c[1]), "+f"(c[2]), "+f"(c[3])
        : "r"(a[0]), "r"(a[1]), "r"(a[2]), "r"(a[3]), "r"(b[0]), "r"(b[1]));
}

// ---------------- tf32 tensor-core GEMM ----------------
// C = A(MxK) @ B(KxN), row-major. BM=BN=128, BK=32, 256 threads (8 warps).
// Warp tile 32x64 -> 2x8 m16n8k8 mmas. Double-buffered smem, reg-staged loads.
// Requires M%128==0, N%128==0, K%32==0 (true for all call sites).
#define BM 128
#define BN 128
#define BK 32
#define PA 36    // As pitch (floats): %32==4  -> conflict-free frag loads
#define PB 136   // Bs pitch (floats): %32==8  -> conflict-free frag loads
#define GEMM_SMEM ((2*BM*PA + 2*BK*PB) * 4)   // 71680 bytes

__global__ void __launch_bounds__(256) gemm_tf32(const float* __restrict__ A,
        const float* __restrict__ B, float* __restrict__ C,
        int M, int N, int K) {
    extern __shared__ unsigned smu[];
    unsigned* As = smu;                 // [2][BM][PA]
    unsigned* Bs = smu + 2 * BM * PA;   // [2][BK][PB]

    const int tid  = threadIdx.x;
    const int lane = tid & 31;
    const int warp = tid >> 5;
    const int wm   = (warp & 3) * 32;
    const int wn   = (warp >> 2) * 64;
    const int bm   = blockIdx.y * BM;
    const int bn   = blockIdx.x * BN;
    const int nk   = K / BK;

    // gmem load coordinates (fixed per thread)
    const int arow = tid >> 3;          // + i*32, i=0..3
    const int acol = (tid & 7) * 4;
    const int brow = tid >> 5;          // + i*8
    const int bcol = (tid & 31) * 4;

    float acc[2][8][4];
    #pragma unroll
    for (int mi = 0; mi < 2; mi++)
        #pragma unroll
        for (int ni = 0; ni < 8; ni++)
            #pragma unroll
            for (int r = 0; r < 4; r++) acc[mi][ni][r] = 0.f;

    // prologue: tile 0 straight into stage 0
    {
        const float* Ab = A + (size_t)bm * K;
        const float* Bb = B + bn;
        #pragma unroll
        for (int i = 0; i < 4; i++) {
            const int r = arow + i * 32;
            float4 v = *(const float4*)(Ab + (size_t)r * K + acol);
            uint4 u = make_uint4(f2tf(v.x), f2tf(v.y), f2tf(v.z), f2tf(v.w));
            *(uint4*)(As + r * PA + acol) = u;
        }
        #pragma unroll
        for (int i = 0; i < 4; i++) {
            const int r = brow + i * 8;
            float4 v = *(const float4*)(Bb + (size_t)r * N + bcol);
            uint4 u = make_uint4(f2tf(v.x), f2tf(v.y), f2tf(v.z), f2tf(v.w));
            *(uint4*)(Bs + r * PB + bcol) = u;
        }
    }
    __syncthreads();

    for (int kt = 0; kt < nk; kt++) {
        float4 ra[4], rb[4];
        const bool more = (kt + 1 < nk);
        if (more) {
            const float* Ab = A + (size_t)bm * K + (kt + 1) * BK;
            const float* Bb = B + (size_t)((kt + 1) * BK) * N + bn;
            #pragma unroll
            for (int i = 0; i < 4; i++)
                ra[i] = *(const float4*)(Ab + (size_t)(arow + i * 32) * K + acol);
            #pragma unroll
            for (int i = 0; i < 4; i++)
                rb[i] = *(const float4*)(Bb + (size_t)(brow + i * 8) * N + bcol);
        }

        // compute current stage
        {
            const unsigned* Ab = As + (kt & 1) * BM * PA;
            const unsigned* Bb = Bs + (kt & 1) * BK * PB;
            #pragma unroll
            for (int ks = 0; ks < BK; ks += 8) {
                unsigned af[2][4], bf[8][2];
                #pragma unroll
                for (int mi = 0; mi < 2; mi++) {
                    const int r = wm + mi * 16 + (lane >> 2);
                    const int c = ks + (lane & 3);
                    af[mi][0] = Ab[r * PA + c];
                    af[mi][1] = Ab[(r + 8) * PA + c];
                    af[mi][2] = Ab[r * PA + c + 4];
                    af[mi][3] = Ab[(r + 8) * PA + c + 4];
                }
                #pragma unroll
                for (int ni = 0; ni < 8; ni++) {
                    const int cn = wn + ni * 8 + (lane >> 2);
                    const int rk = ks + (lane & 3);
                    bf[ni][0] = Bb[rk * PB + cn];
                    bf[ni][1] = Bb[(rk + 4) * PB + cn];
                }
                #pragma unroll
                for (int mi = 0; mi < 2; mi++)
                    #pragma unroll
                    for (int ni = 0; ni < 8; ni++)
                        mma_tf32(acc[mi][ni], af[mi], bf[ni]);
            }
        }

        if (more) {
            unsigned* Ad = As + ((kt + 1) & 1) * BM * PA;
            unsigned* Bd = Bs + ((kt + 1) & 1) * BK * PB;
            #pragma unroll
            for (int i = 0; i < 4; i++) {
                uint4 u = make_uint4(f2tf(ra[i].x), f2tf(ra[i].y), f2tf(ra[i].z), f2tf(ra[i].w));
                *(uint4*)(Ad + (arow + i * 32) * PA + acol) = u;
            }
            #pragma unroll
            for (int i = 0; i < 4; i++) {
                uint4 u = make_uint4(f2tf(rb[i].x), f2tf(rb[i].y), f2tf(rb[i].z), f2tf(rb[i].w));
                *(uint4*)(Bd + (brow + i * 8) * PB + bcol) = u;
            }
        }
        __syncthreads();
    }

    // epilogue
    #pragma unroll
    for (int mi = 0; mi < 2; mi++) {
        const int r0 = bm + wm + mi * 16 + (lane >> 2);
        #pragma unroll
        for (int ni = 0; ni < 8; ni++) {
            const int c0 = bn + wn + ni * 8 + 2 * (lane & 3);
            *(float2*)(C + (size_t)r0 * N + c0)       = make_float2(acc[mi][ni][0], acc[mi][ni][1]);
            *(float2*)(C + (size_t)(r0 + 8) * N + c0) = make_float2(acc[mi][ni][2], acc[mi][ni][3]);
        }
    }
}

// ---------------- gate projection: g = hs @ Wg (N=4) ----------------
// one block per s-row (128 threads = 4 warps), warp w computes column w.
__global__ void gate_proj(const float* __restrict__ hs, const float* __restrict__ Wg) {
    const int s = blockIdx.x;
    const int w = threadIdx.x >> 5, l = threadIdx.x & 31;
    const float* row = hs + (size_t)s * HID_;
    float acc = 0.f;
    for (int k = l; k < HID_; k += 32)
        acc = fmaf(row[k], Wg[k * HKV_ + w], acc);
    #pragma unroll
    for (int o = 16; o > 0; o >>= 1)
        acc += __shfl_down_sync(0xffffffffu, acc, o);
    if (l == 0) g_g[s * HKV_ + w] = acc;
}

// ---------------- log-sigmoid + parallel cumsum (one block per kv head) ----
__global__ void gcumsum_kernel() {
    __shared__ float ps[256];
    const int kv = blockIdx.x;
    const int t = threadIdx.x;      // 256 threads, 8 contiguous elems each
    float loc[8]; float s = 0.f;
    #pragma unroll
    for (int i = 0; i < 8; i++) {
        const float x = g_g[(t * 8 + i) * HKV_ + kv];
        const float ls = (x > 0.f) ? -log1pf(__expf(-x)) : x - log1pf(__expf(x));
        loc[i] = ls; s += ls;
    }
    ps[t] = s; __syncthreads();
    for (int o = 1; o < 256; o <<= 1) {
        const float v = (t >= o) ? ps[t - o] : 0.f;
        __syncthreads();
        ps[t] += v;
        __syncthreads();
    }
    float run = (t > 0) ? ps[t - 1] : 0.f;
    #pragma unroll
    for (int i = 0; i < 8; i++) {
        run += loc[i];
        g_gc[kv * S_ + t * 8 + i] = run;
    }
}

// ---------------- RoPE (in place) ----------------
__global__ void rope_kernel(float* __restrict__ x, const float* __restrict__ cosb,
                            const float* __restrict__ sinb, int nheads) {
    const int idx = blockIdx.x * blockDim.x + threadIdx.x;
    const int total = S_ * nheads * 64;
    if (idx >= total) return;
    const int d = idx % 64;
    const int h = (idx / 64) % nheads;
    const int s = idx / (64 * nheads);
    const float c  = cosb[s * 128 + d];
    const float sn = sinb[s * 128 + d];
    float* row = x + (size_t)s * nheads * 128 + h * 128;
    const float x0 = row[d], x1 = row[d + 64];
    row[d]      = x0 * c - x1 * sn;
    row[d + 64] = x1 * c + x0 * sn;
}

// ---------------- causal power attention with exact decay truncation ------
__global__ void attn_kernel() {
    extern __shared__ float sm[];
    float* Qs  = sm;                 // 64*PAD
    float* Ks  = Qs + 64 * PAD;      // 64*PAD
    float* Vs  = Ks + 64 * PAD;      // 64*PAD
    float* Ss  = Vs + 64 * PAD;      // 64*65
    float* Gq  = Ss + 64 * 65;       // 64
    float* Gk  = Gq + 64;            // 64
    float* den = Gk + 64;            // 64

    const int qb = blockIdx.x;
    const int h  = blockIdx.y;
    const int kv = h / GROUPS_;
    const int tx = threadIdx.x, ty = threadIdx.y;
    const int tid = ty * 16 + tx;

    for (int e = tid; e < 64 * 128; e += 256) {
        const int r = e >> 7, d = e & 127;
        Qs[r * PAD + d] = g_q[(size_t)(qb * 64 + r) * (H_ * D_) + h * D_ + d];
    }
    if (tid < 64) {
        Gq[tid]  = g_gc[kv * S_ + qb * 64 + tid];
        den[tid] = 0.f;
    }
    __syncthreads();

    float gq[4];
    #pragma unroll
    for (int i = 0; i < 4; i++) gq[i] = Gq[ty * 4 + i];
    const float Gq0 = Gq[0];   // max G over query tile (G decreasing)

    float o[4][8] = {};

    for (int kb = qb; kb >= 0; kb--) {
        // exact tile-level skip: best-case logdecay below cutoff -> all older
        // blocks are even smaller (G monotone decreasing) -> break.
        if (kb < qb) {
            const float gkLast = g_gc[kv * S_ + kb * 64 + 63];
            if (Gq0 - gkLast < DECAY_CUT) break;
        }
        __syncthreads();   // previous iteration done reading Ks/Vs/Ss
        for (int e = tid; e < 64 * 128; e += 256) {
            const int r = e >> 7, d = e & 127;
            const int gr = kb * 64 + r;
            Ks[r * PAD + d] = g_k[(size_t)gr * (HKV_ * D_) + kv * D_ + d];
            Vs[r * PAD + d] = g_v[(size_t)gr * (HKV_ * D_) + kv * D_ + d];
        }
        if (tid < 64) Gk[tid] = g_gc[kv * S_ + kb * 64 + tid];
        __syncthreads();

        float s[4][4] = {};
        #pragma unroll 4
        for (int d = 0; d < 128; d++) {
            float a[4], b[4];
            #pragma unroll
            for (int i = 0; i < 4; i++) a[i] = Qs[(ty * 4 + i) * PAD + d];
            #pragma unroll
            for (int u = 0; u < 4; u++) b[u] = Ks[(tx + 16 * u) * PAD + d];
            #pragma unroll
            for (int i = 0; i < 4; i++)
                #pragma unroll
                for (int u = 0; u < 4; u++)
                    s[i][u] = fmaf(a[i], b[u], s[i][u]);
        }
        #pragma unroll
        for (int i = 0; i < 4; i++) {
            const int gi = qb * 64 + ty * 4 + i;
            #pragma unroll
            for (int u = 0; u < 4; u++) {
                const int j  = tx + 16 * u;
                const int gj = kb * 64 + j;
                float val = 0.f;
                if (gj <= gi) {
                    const float t = s[i][u] * SCALE_;
                    val = t * t * __expf(gq[i] - Gk[j]);
                }
                Ss[(ty * 4 + i) * 65 + j] = val;
            }
        }
        __syncthreads();

        if (tid < 64) {
            float rs = 0.f;
            #pragma unroll 8
            for (int j = 0; j < 64; j++) rs += Ss[tid * 65 + j];
            den[tid] += rs;
        }

        #pragma unroll 2
        for (int j = 0; j < 64; j++) {
            float sv[4], vv[8];
            #pragma unroll
            for (int i = 0; i < 4; i++) sv[i] = Ss[(ty * 4 + i) * 65 + j];
            #pragma unroll
            for (int u = 0; u < 8; u++) vv[u] = Vs[j * PAD + tx + 16 * u];
            #pragma unroll
            for (int i = 0; i < 4; i++)
                #pragma unroll
                for (int u = 0; u < 8; u++)
                    o[i][u] = fmaf(sv[i], vv[u], o[i][u]);
        }
    }
    __syncthreads();

    #pragma unroll
    for (int i = 0; i < 4; i++) {
        const float inv = 1.f / fmaxf(den[ty * 4 + i], 1.f);
        const int gi = qb * 64 + ty * 4 + i;
        #pragma unroll
        for (int u = 0; u < 8; u++)
            g_attn[(size_t)gi * (H_ * D_) + h * D_ + tx + 16 * u] = o[i][u] * inv;
    }
}

// ---------------- launch ----------------
extern "C" void kernel_launch(void* const* d_in, const int* in_sizes, int n_in,
                              void* d_out, int out_size) {
    (void)in_sizes; (void)n_in; (void)out_size;
    const float* hs   = (const float*)d_in[0];
    const float* cosb = (const float*)d_in[1];
    const float* sinb = (const float*)d_in[2];
    const float* Wq   = (const float*)d_in[3];
    const float* Wk   = (const float*)d_in[4];
    const float* Wv   = (const float*)d_in[5];
    const float* Wg   = (const float*)d_in[6];
    const float* Wo   = (const float*)d_in[7];
    float* out = (float*)d_out;

    float *q, *k, *v, *attn;
    cudaGetSymbolAddress((void**)&q,    g_q);
    cudaGetSymbolAddress((void**)&k,    g_k);
    cudaGetSymbolAddress((void**)&v,    g_v);
    cudaGetSymbolAddress((void**)&attn, g_attn);

    cudaFuncSetAttribute(gemm_tf32, cudaFuncAttributeMaxDynamicSharedMemorySize, GEMM_SMEM);

    // projections (tensor cores)
    gemm_tf32<<<dim3((H_*D_)  / BN, S_ / BM), 256, GEMM_SMEM>>>(hs, Wq, q, S_, H_*D_,   HID_);
    gemm_tf32<<<dim3((HKV_*D_)/ BN, S_ / BM), 256, GEMM_SMEM>>>(hs, Wk, k, S_, HKV_*D_, HID_);
    gemm_tf32<<<dim3((HKV_*D_)/ BN, S_ / BM), 256, GEMM_SMEM>>>(hs, Wv, v, S_, HKV_*D_, HID_);
    gate_proj<<<S_, 128>>>(hs, Wg);

    // RoPE
    rope_kernel<<<(S_*H_*64   + 255) / 256, 256>>>(q, cosb, sinb, H_);
    rope_kernel<<<(S_*HKV_*64 + 255) / 256, 256>>>(k, cosb, sinb, HKV_);

    // gate log-sigmoid + cumsum
    gcumsum_kernel<<<HKV_, 256>>>();

    // attention (decay-truncated)
    const size_t smem = (size_t)(3 * 64 * PAD + 64 * 65 + 3 * 64) * sizeof(float);
    cudaFuncSetAttribute(attn_kernel, cudaFuncAttributeMaxDynamicSharedMemorySize, (int)smem);
    attn_kernel<<<dim3(S_ / 64, H_), dim3(16, 16), smem>>>();

    // output projection (tensor cores)
    gemm_tf32<<<dim3(HID_ / BN, S_ / BM), 256, GEMM_SMEM>>>(attn, Wo, out, S_, HID_, H_*D_);
}

// round 4
// speedup vs baseline: 7.8692x; 1.3399x over previous
#include <cuda_runtime.h>
#include <math.h>

#define S_     2048
#define HID_   2048
#define H_     16
#define HKV_   4
#define D_     128
#define GROUPS_ 4
#define SCALE_ 0.08838834764831845f   // 128^-0.5

#define PAD 129     // attn smem row pitch
#define DECAY_CUT (-40.0f)

// ---------------- scratch (no cudaMalloc allowed) ----------------
__device__ float g_q   [S_*H_*D_];
__device__ float g_k   [S_*HKV_*D_];
__device__ float g_v   [S_*HKV_*D_];
__device__ float g_g   [S_*HKV_];
__device__ float g_gc  [HKV_*S_];
__device__ float g_attn[S_*H_*D_];
// tf32-prerounded copies (stored as f32 with low mantissa bits cleared)
__device__ float g_hsr [S_*HID_];
__device__ float g_wqr [HID_*H_*D_];
__device__ float g_wkr [HID_*HKV_*D_];
__device__ float g_wvr [HID_*HKV_*D_];
__device__ float g_wor [H_*D_*HID_];

// ---------------- tf32 helpers ----------------
__device__ __forceinline__ unsigned f2tf(float x) {
    unsigned r; asm("cvt.rna.tf32.f32 %0, %1;" : "=r"(r) : "f"(x)); return r;
}
__device__ __forceinline__ void mma_tf32(float c[4], const unsigned a[4], const unsigned b[2]) {
    asm volatile("mma.sync.aligned.m16n8k8.row.col.f32.tf32.tf32.f32 "
        "{%0,%1,%2,%3},{%4,%5,%6,%7},{%8,%9},{%0,%1,%2,%3};"
        : "+f"(c[0]), "+f"(c[1]), "+f"(c[2]), "+f"(c[3])
        : "r"(a[0]), "r"(a[1]), "r"(a[2]), "r"(a[3]), "r"(b[0]), "r"(b[1]));
}
__device__ __forceinline__ void cpa16(void* sp, const void* gp) {
    unsigned s = (unsigned)__cvta_generic_to_shared(sp);
    asm volatile("cp.async.cg.shared.global [%0], [%1], 16;" :: "r"(s), "l"(gp));
}

// ---------------- pre-round f32 -> tf32(rna) bits ----------------
__global__ void preround(const float* __restrict__ s, float* __restrict__ d) {
    const size_t i = ((size_t)blockIdx.x * 256 + threadIdx.x) * 4;
    float4 v = *(const float4*)(s + i);
    v.x = __uint_as_float(f2tf(v.x));
    v.y = __uint_as_float(f2tf(v.y));
    v.z = __uint_as_float(f2tf(v.z));
    v.w = __uint_as_float(f2tf(v.w));
    *(float4*)(d + i) = v;
}

// ---------------- tf32 tensor-core GEMM core ----------------
// C = A(2048 x 2048) @ B(2048 x N) block at (bm, bn). Inputs pre-rounded to
// tf32 (so raw-bit mma == rna). BM=BN=128, BK=32, 256 threads, 3-stage cp.async.
#define BM 128
#define BN 128
#define BK 32
#define PA 36
#define PB 136
#define NK 64                       // 2048 / BK
#define STG_A (BM*PA)
#define STG_B (BK*PB)
#define GEMM_SMEM3 (3*(STG_A+STG_B)*4)   // 107520 B

__device__ __forceinline__ void gemm_issue(const float* __restrict__ A,
        const float* __restrict__ B, int N, int bm, int bn,
        float* As, float* Bs, int kt,
        int arow, int acol, int brow, int bcol) {
    float* Ad = As + (kt % 3) * STG_A;
    const float* Ag = A + (size_t)bm * 2048 + kt * BK;
    #pragma unroll
    for (int i = 0; i < 4; i++) {
        const int r = arow + i * 32;
        cpa16(Ad + r * PA + acol, Ag + (size_t)r * 2048 + acol);
    }
    float* Bd = Bs + (kt % 3) * STG_B;
    const float* Bg = B + (size_t)(kt * BK) * N + bn;
    #pragma unroll
    for (int i = 0; i < 4; i++) {
        const int r = brow + i * 8;
        cpa16(Bd + r * PB + bcol, Bg + (size_t)r * N + bcol);
    }
    asm volatile("cp.async.commit_group;");
}

__device__ __forceinline__ void gemm_core(const float* __restrict__ A,
        const float* __restrict__ B, float* __restrict__ C,
        int N, int bm, int bn, float* As, float* Bs) {
    const int tid  = threadIdx.x;
    const int lane = tid & 31;
    const int warp = tid >> 5;
    const int wm   = (warp & 3) * 32;
    const int wn   = (warp >> 2) * 64;
    const int arow = tid >> 3, acol = (tid & 7) * 4;
    const int brow = tid >> 5, bcol = (tid & 31) * 4;

    float acc[2][8][4];
    #pragma unroll
    for (int mi = 0; mi < 2; mi++)
        #pragma unroll
        for (int ni = 0; ni < 8; ni++)
            #pragma unroll
            for (int r = 0; r < 4; r++) acc[mi][ni][r] = 0.f;

    gemm_issue(A, B, N, bm, bn, As, Bs, 0, arow, acol, brow, bcol);
    gemm_issue(A, B, N, bm, bn, As, Bs, 1, arow, acol, brow, bcol);

    for (int kt = 0; kt < NK; kt++) {
        asm volatile("cp.async.wait_group 1;");
        __syncthreads();

        const float* Ab = As + (kt % 3) * STG_A;
        const float* Bb = Bs + (kt % 3) * STG_B;
        #pragma unroll
        for (int ks = 0; ks < BK; ks += 8) {
            unsigned af[2][4], bf[8][2];
            #pragma unroll
            for (int mi = 0; mi < 2; mi++) {
                const int r = wm + mi * 16 + (lane >> 2);
                const int c = ks + (lane & 3);
                af[mi][0] = __float_as_uint(Ab[r * PA + c]);
                af[mi][1] = __float_as_uint(Ab[(r + 8) * PA + c]);
                af[mi][2] = __float_as_uint(Ab[r * PA + c + 4]);
                af[mi][3] = __float_as_uint(Ab[(r + 8) * PA + c + 4]);
            }
            #pragma unroll
            for (int ni = 0; ni < 8; ni++) {
                const int cn = wn + ni * 8 + (lane >> 2);
                const int rk = ks + (lane & 3);
                bf[ni][0] = __float_as_uint(Bb[rk * PB + cn]);
                bf[ni][1] = __float_as_uint(Bb[(rk + 4) * PB + cn]);
            }
            #pragma unroll
            for (int mi = 0; mi < 2; mi++)
                #pragma unroll
                for (int ni = 0; ni < 8; ni++)
                    mma_tf32(acc[mi][ni], af[mi], bf[ni]);
        }
        __syncthreads();

        if (kt + 2 < NK)
            gemm_issue(A, B, N, bm, bn, As, Bs, kt + 2, arow, acol, brow, bcol);
        else
            asm volatile("cp.async.commit_group;");   // empty group keeps count
    }

    #pragma unroll
    for (int mi = 0; mi < 2; mi++) {
        const int r0 = bm + wm + mi * 16 + (lane >> 2);
        #pragma unroll
        for (int ni = 0; ni < 8; ni++) {
            const int c0 = bn + wn + ni * 8 + 2 * (lane & 3);
            *(float2*)(C + (size_t)r0 * N + c0)       = make_float2(acc[mi][ni][0], acc[mi][ni][1]);
            *(float2*)(C + (size_t)(r0 + 8) * N + c0) = make_float2(acc[mi][ni][2], acc[mi][ni][3]);
        }
    }
}

// fused Q/K/V projection: column blocks 0-15 -> Q, 16-19 -> K, 20-23 -> V
__global__ void __launch_bounds__(256) gemm_qkv(const float* __restrict__ A,
        const float* __restrict__ Bq, const float* __restrict__ Bk,
        const float* __restrict__ Bv) {
    extern __shared__ float smf[];
    const int bx = blockIdx.x;
    const float* Bm; float* Cm; int N, bn;
    if (bx < 16)      { Bm = Bq; Cm = g_q; N = 2048; bn = bx * 128; }
    else if (bx < 20) { Bm = Bk; Cm = g_k; N = 512;  bn = (bx - 16) * 128; }
    else              { Bm = Bv; Cm = g_v; N = 512;  bn = (bx - 20) * 128; }
    gemm_core(A, Bm, Cm, N, blockIdx.y * BM, bn, smf, smf + 3 * STG_A);
}

__global__ void __launch_bounds__(256) gemm_wo(const float* __restrict__ A,
        const float* __restrict__ B, float* __restrict__ C) {
    extern __shared__ float smf[];
    gemm_core(A, B, C, HID_, blockIdx.y * BM, blockIdx.x * BN, smf, smf + 3 * STG_A);
}

// ---------------- gate projection (exact fp32) ----------------
__global__ void gate_proj(const float* __restrict__ hs, const float* __restrict__ Wg) {
    const int s = blockIdx.x;
    const int w = threadIdx.x >> 5, l = threadIdx.x & 31;
    const float* row = hs + (size_t)s * HID_;
    float acc = 0.f;
    for (int k = l; k < HID_; k += 32)
        acc = fmaf(row[k], Wg[k * HKV_ + w], acc);
    #pragma unroll
    for (int o = 16; o > 0; o >>= 1)
        acc += __shfl_down_sync(0xffffffffu, acc, o);
    if (l == 0) g_g[s * HKV_ + w] = acc;
}

// ---------------- log-sigmoid + parallel cumsum ----------------
__global__ void gcumsum_kernel() {
    __shared__ float ps[256];
    const int kv = blockIdx.x;
    const int t = threadIdx.x;
    float loc[8]; float s = 0.f;
    #pragma unroll
    for (int i = 0; i < 8; i++) {
        const float x = g_g[(t * 8 + i) * HKV_ + kv];
        const float ls = (x > 0.f) ? -log1pf(__expf(-x)) : x - log1pf(__expf(x));
        loc[i] = ls; s += ls;
    }
    ps[t] = s; __syncthreads();
    for (int o = 1; o < 256; o <<= 1) {
        const float v = (t >= o) ? ps[t - o] : 0.f;
        __syncthreads();
        ps[t] += v;
        __syncthreads();
    }
    float run = (t > 0) ? ps[t - 1] : 0.f;
    #pragma unroll
    for (int i = 0; i < 8; i++) {
        run += loc[i];
        g_gc[kv * S_ + t * 8 + i] = run;
    }
}

// ---------------- RoPE (in place) ----------------
__global__ void rope_kernel(float* __restrict__ x, const float* __restrict__ cosb,
                            const float* __restrict__ sinb, int nheads) {
    const int idx = blockIdx.x * blockDim.x + threadIdx.x;
    const int total = S_ * nheads * 64;
    if (idx >= total) return;
    const int d = idx % 64;
    const int h = (idx / 64) % nheads;
    const int s = idx / (64 * nheads);
    const float c  = cosb[s * 128 + d];
    const float sn = sinb[s * 128 + d];
    float* row = x + (size_t)s * nheads * 128 + h * 128;
    const float x0 = row[d], x1 = row[d + 64];
    row[d]      = x0 * c - x1 * sn;
    row[d + 64] = x1 * c + x0 * sn;
}

// ---------------- causal power attention with exact decay truncation ------
__global__ void attn_kernel() {
    extern __shared__ float sm[];
    float* Qs  = sm;
    float* Ks  = Qs + 64 * PAD;
    float* Vs  = Ks + 64 * PAD;
    float* Ss  = Vs + 64 * PAD;
    float* Gq  = Ss + 64 * 65;
    float* Gk  = Gq + 64;
    float* den = Gk + 64;

    const int qb = blockIdx.x;
    const int h  = blockIdx.y;
    const int kv = h / GROUPS_;
    const int tx = threadIdx.x, ty = threadIdx.y;
    const int tid = ty * 16 + tx;

    for (int e = tid; e < 64 * 128; e += 256) {
        const int r = e >> 7, d = e & 127;
        Qs[r * PAD + d] = g_q[(size_t)(qb * 64 + r) * (H_ * D_) + h * D_ + d];
    }
    if (tid < 64) {
        Gq[tid]  = g_gc[kv * S_ + qb * 64 + tid];
        den[tid] = 0.f;
    }
    __syncthreads();

    float gq[4];
    #pragma unroll
    for (int i = 0; i < 4; i++) gq[i] = Gq[ty * 4 + i];
    const float Gq0 = Gq[0];

    float o[4][8] = {};

    for (int kb = qb; kb >= 0; kb--) {
        if (kb < qb) {
            const float gkLast = g_gc[kv * S_ + kb * 64 + 63];
            if (Gq0 - gkLast < DECAY_CUT) break;
        }
        __syncthreads();
        for (int e = tid; e < 64 * 128; e += 256) {
            const int r = e >> 7, d = e & 127;
            const int gr = kb * 64 + r;
            Ks[r * PAD + d] = g_k[(size_t)gr * (HKV_ * D_) + kv * D_ + d];
            Vs[r * PAD + d] = g_v[(size_t)gr * (HKV_ * D_) + kv * D_ + d];
        }
        if (tid < 64) Gk[tid] = g_gc[kv * S_ + kb * 64 + tid];
        __syncthreads();

        float s[4][4] = {};
        #pragma unroll 4
        for (int d = 0; d < 128; d++) {
            float a[4], b[4];
            #pragma unroll
            for (int i = 0; i < 4; i++) a[i] = Qs[(ty * 4 + i) * PAD + d];
            #pragma unroll
            for (int u = 0; u < 4; u++) b[u] = Ks[(tx + 16 * u) * PAD + d];
            #pragma unroll
            for (int i = 0; i < 4; i++)
                #pragma unroll
                for (int u = 0; u < 4; u++)
                    s[i][u] = fmaf(a[i], b[u], s[i][u]);
        }
        #pragma unroll
        for (int i = 0; i < 4; i++) {
            const int gi = qb * 64 + ty * 4 + i;
            #pragma unroll
            for (int u = 0; u < 4; u++) {
                const int j  = tx + 16 * u;
                const int gj = kb * 64 + j;
                float val = 0.f;
                if (gj <= gi) {
                    const float t = s[i][u] * SCALE_;
                    val = t * t * __expf(gq[i] - Gk[j]);
                }
                Ss[(ty * 4 + i) * 65 + j] = val;
            }
        }
        __syncthreads();

        if (tid < 64) {
            float rs = 0.f;
            #pragma unroll 8
            for (int j = 0; j < 64; j++) rs += Ss[tid * 65 + j];
            den[tid] += rs;
        }

        #pragma unroll 2
        for (int j = 0; j < 64; j++) {
            float sv[4], vv[8];
            #pragma unroll
            for (int i = 0; i < 4; i++) sv[i] = Ss[(ty * 4 + i) * 65 + j];
            #pragma unroll
            for (int u = 0; u < 8; u++) vv[u] = Vs[j * PAD + tx + 16 * u];
            #pragma unroll
            for (int i = 0; i < 4; i++)
                #pragma unroll
                for (int u = 0; u < 8; u++)
                    o[i][u] = fmaf(sv[i], vv[u], o[i][u]);
        }
    }
    __syncthreads();

    #pragma unroll
    for (int i = 0; i < 4; i++) {
        const float inv = 1.f / fmaxf(den[ty * 4 + i], 1.f);
        const int gi = qb * 64 + ty * 4 + i;
        #pragma unroll
        for (int u = 0; u < 8; u++)
            g_attn[(size_t)gi * (H_ * D_) + h * D_ + tx + 16 * u] =
                __uint_as_float(f2tf(o[i][u] * inv));   // pre-rounded for Wo gemm
    }
}

// ---------------- launch ----------------
extern "C" void kernel_launch(void* const* d_in, const int* in_sizes, int n_in,
                              void* d_out, int out_size) {
    (void)in_sizes; (void)n_in; (void)out_size;
    const float* hs   = (const float*)d_in[0];
    const float* cosb = (const float*)d_in[1];
    const float* sinb = (const float*)d_in[2];
    const float* Wq   = (const float*)d_in[3];
    const float* Wk   = (const float*)d_in[4];
    const float* Wv   = (const float*)d_in[5];
    const float* Wg   = (const float*)d_in[6];
    const float* Wo   = (const float*)d_in[7];
    float* out = (float*)d_out;

    float *q, *k, *attn, *hsr, *wqr, *wkr, *wvr, *wor;
    cudaGetSymbolAddress((void**)&q,    g_q);
    cudaGetSymbolAddress((void**)&k,    g_k);
    cudaGetSymbolAddress((void**)&attn, g_attn);
    cudaGetSymbolAddress((void**)&hsr,  g_hsr);
    cudaGetSymbolAddress((void**)&wqr,  g_wqr);
    cudaGetSymbolAddress((void**)&wkr,  g_wkr);
    cudaGetSymbolAddress((void**)&wvr,  g_wvr);
    cudaGetSymbolAddress((void**)&wor,  g_wor);

    static cudaStream_t s1 = nullptr, s2 = nullptr;
    static cudaEvent_t ev0, ev1, ev2;
    if (!s1) {
        cudaStreamCreateWithFlags(&s1, cudaStreamNonBlocking);
        cudaStreamCreateWithFlags(&s2, cudaStreamNonBlocking);
        cudaEventCreateWithFlags(&ev0, cudaEventDisableTiming);
        cudaEventCreateWithFlags(&ev1, cudaEventDisableTiming);
        cudaEventCreateWithFlags(&ev2, cudaEventDisableTiming);
    }

    cudaFuncSetAttribute(gemm_qkv, cudaFuncAttributeMaxDynamicSharedMemorySize, GEMM_SMEM3);
    cudaFuncSetAttribute(gemm_wo,  cudaFuncAttributeMaxDynamicSharedMemorySize, GEMM_SMEM3);
    const size_t asmem = (size_t)(3 * 64 * PAD + 64 * 65 + 3 * 64) * sizeof(float);
    cudaFuncSetAttribute(attn_kernel, cudaFuncAttributeMaxDynamicSharedMemorySize, (int)asmem);

    cudaEventRecord(ev0, 0);

    // side stream 2: pre-round Wo (only needed before the last GEMM)
    cudaStreamWaitEvent(s2, ev0, 0);
    preround<<<(H_*D_*HID_) / 1024, 256, 0, s2>>>(Wo, wor);
    cudaEventRecord(ev2, s2);

    // side stream 1: gate path (exact fp32)
    cudaStreamWaitEvent(s1, ev0, 0);
    gate_proj<<<S_, 128, 0, s1>>>(hs, Wg);
    gcumsum_kernel<<<HKV_, 256, 0, s1>>>();
    cudaEventRecord(ev1, s1);

    // main stream: pre-round inputs, fused QKV GEMM, RoPE
    preround<<<(S_*HID_)      / 1024, 256>>>(hs, hsr);
    preround<<<(HID_*H_*D_)   / 1024, 256>>>(Wq, wqr);
    preround<<<(HID_*HKV_*D_) / 1024, 256>>>(Wk, wkr);
    preround<<<(HID_*HKV_*D_) / 1024, 256>>>(Wv, wvr);
    gemm_qkv<<<dim3(24, S_ / BM), 256, GEMM_SMEM3>>>(hsr, wqr, wkr, wvr);
    rope_kernel<<<(S_*H_*64   + 255) / 256, 256>>>(q, cosb, sinb, H_);
    rope_kernel<<<(S_*HKV_*64 + 255) / 256, 256>>>(k, cosb, sinb, HKV_);

    // join gate path, run attention
    cudaStreamWaitEvent(0, ev1, 0);
    attn_kernel<<<dim3(S_ / 64, H_), dim3(16, 16), asmem>>>();

    // join Wo pre-round, output projection
    cudaStreamWaitEvent(0, ev2, 0);
    gemm_wo<<<dim3(HID_ / BN, S_ / BM), 256, GEMM_SMEM3>>>(attn, wor, out);
}

// round 6
// speedup vs baseline: 9.0393x; 1.1487x over previous
#include <cuda_runtime.h>
#include <math.h>

#define S_     2048
#define HID_   2048
#define H_     16
#define HKV_   4
#define D_     128
#define GROUPS_ 4
#define SCALE_ 0.08838834764831845f   // 128^-0.5
#define DECAY_CUT (-40.0f)

// ---------------- scratch (no cudaMalloc allowed) ----------------
__device__ float g_q   [S_*H_*D_];
__device__ float g_k   [S_*HKV_*D_];
__device__ float g_v   [S_*HKV_*D_];
__device__ float g_g   [S_*HKV_];
__device__ float g_gc  [HKV_*S_];
__device__ float g_attn[S_*H_*D_];
__device__ float g_hsr [S_*HID_];
__device__ float g_wqr [HID_*H_*D_];
__device__ float g_wkr [HID_*HKV_*D_];
__device__ float g_wvr [HID_*HKV_*D_];
__device__ float g_wor [H_*D_*HID_];

// ---------------- tf32 helpers ----------------
__device__ __forceinline__ unsigned f2tf(float x) {
    unsigned r; asm("cvt.rna.tf32.f32 %0, %1;" : "=r"(r) : "f"(x)); return r;
}
__device__ __forceinline__ void mma_tf32(float c[4], const unsigned a[4], const unsigned b[2]) {
    asm volatile("mma.sync.aligned.m16n8k8.row.col.f32.tf32.tf32.f32 "
        "{%0,%1,%2,%3},{%4,%5,%6,%7},{%8,%9},{%0,%1,%2,%3};"
        : "+f"(c[0]), "+f"(c[1]), "+f"(c[2]), "+f"(c[3])
        : "r"(a[0]), "r"(a[1]), "r"(a[2]), "r"(a[3]), "r"(b[0]), "r"(b[1]));
}
// split x into hi (tf32-truncated bits, == what mma sees) + lo (exact residual)
__device__ __forceinline__ void split2(float x, unsigned& hi, unsigned& lo) {
    const unsigned h = __float_as_uint(x) & 0xffffe000u;
    hi = h;
    lo = __float_as_uint(x - __uint_as_float(h));
}
__device__ __forceinline__ void cpa16(void* sp, const void* gp) {
    unsigned s = (unsigned)__cvta_generic_to_shared(sp);
    asm volatile("cp.async.cg.shared.global [%0], [%1], 16;" :: "r"(s), "l"(gp));
}

// ---------------- pre-round f32 -> tf32(rna) bits ----------------
__global__ void preround(const float* __restrict__ s, float* __restrict__ d) {
    const size_t i = ((size_t)blockIdx.x * 256 + threadIdx.x) * 4;
    float4 v = *(const float4*)(s + i);
    v.x = __uint_as_float(f2tf(v.x));
    v.y = __uint_as_float(f2tf(v.y));
    v.z = __uint_as_float(f2tf(v.z));
    v.w = __uint_as_float(f2tf(v.w));
    *(float4*)(d + i) = v;
}

// ---------------- tf32 tensor-core GEMM ----------------
#define BM 128
#define BN 128
#define BK 32
#define PA 36
#define PB 136
#define NK 64
#define STG_A (BM*PA)
#define STG_B (BK*PB)
#define GEMM_SMEM3 (3*(STG_A+STG_B)*4)   // 107520 B

__device__ __forceinline__ void gemm_issue(const float* __restrict__ A,
        const float* __restrict__ B, int N, int bm, int bn,
        float* As, float* Bs, int kt,
        int arow, int acol, int brow, int bcol) {
    float* Ad = As + (kt % 3) * STG_A;
    const float* Ag = A + (size_t)bm * 2048 + kt * BK;
    #pragma unroll
    for (int i = 0; i < 4; i++) {
        const int r = arow + i * 32;
        cpa16(Ad + r * PA + acol, Ag + (size_t)r * 2048 + acol);
    }
    float* Bd = Bs + (kt % 3) * STG_B;
    const float* Bg = B + (size_t)(kt * BK) * N + bn;
    #pragma unroll
    for (int i = 0; i < 4; i++) {
        const int r = brow + i * 8;
        cpa16(Bd + r * PB + bcol, Bg + (size_t)r * N + bcol);
    }
    asm volatile("cp.async.commit_group;");
}

__device__ __forceinline__ void gemm_core(const float* __restrict__ A,
        const float* __restrict__ B, float* __restrict__ C,
        int N, int bm, int bn, float* As, float* Bs) {
    const int tid  = threadIdx.x;
    const int lane = tid & 31;
    const int warp = tid >> 5;
    const int wm   = (warp & 3) * 32;
    const int wn   = (warp >> 2) * 64;
    const int arow = tid >> 3, acol = (tid & 7) * 4;
    const int brow = tid >> 5, bcol = (tid & 31) * 4;

    float acc[2][8][4];
    #pragma unroll
    for (int mi = 0; mi < 2; mi++)
        #pragma unroll
        for (int ni = 0; ni < 8; ni++)
            #pragma unroll
            for (int r = 0; r < 4; r++) acc[mi][ni][r] = 0.f;

    gemm_issue(A, B, N, bm, bn, As, Bs, 0, arow, acol, brow, bcol);
    gemm_issue(A, B, N, bm, bn, As, Bs, 1, arow, acol, brow, bcol);

    for (int kt = 0; kt < NK; kt++) {
        asm volatile("cp.async.wait_group 1;");
        __syncthreads();

        const float* Ab = As + (kt % 3) * STG_A;
        const float* Bb = Bs + (kt % 3) * STG_B;
        #pragma unroll
        for (int ks = 0; ks < BK; ks += 8) {
            unsigned af[2][4], bf[8][2];
            #pragma unroll
            for (int mi = 0; mi < 2; mi++) {
                const int r = wm + mi * 16 + (lane >> 2);
                const int c = ks + (lane & 3);
                af[mi][0] = __float_as_uint(Ab[r * PA + c]);
                af[mi][1] = __float_as_uint(Ab[(r + 8) * PA + c]);
                af[mi][2] = __float_as_uint(Ab[r * PA + c + 4]);
                af[mi][3] = __float_as_uint(Ab[(r + 8) * PA + c + 4]);
            }
            #pragma unroll
            for (int ni = 0; ni < 8; ni++) {
                const int cn = wn + ni * 8 + (lane >> 2);
                const int rk = ks + (lane & 3);
                bf[ni][0] = __float_as_uint(Bb[rk * PB + cn]);
                bf[ni][1] = __float_as_uint(Bb[(rk + 4) * PB + cn]);
            }
            #pragma unroll
            for (int mi = 0; mi < 2; mi++)
                #pragma unroll
                for (int ni = 0; ni < 8; ni++)
                    mma_tf32(acc[mi][ni], af[mi], bf[ni]);
        }
        __syncthreads();

        if (kt + 2 < NK)
            gemm_issue(A, B, N, bm, bn, As, Bs, kt + 2, arow, acol, brow, bcol);
        else
            asm volatile("cp.async.commit_group;");
    }

    #pragma unroll
    for (int mi = 0; mi < 2; mi++) {
        const int r0 = bm + wm + mi * 16 + (lane >> 2);
        #pragma unroll
        for (int ni = 0; ni < 8; ni++) {
            const int c0 = bn + wn + ni * 8 + 2 * (lane & 3);
            *(float2*)(C + (size_t)r0 * N + c0)       = make_float2(acc[mi][ni][0], acc[mi][ni][1]);
            *(float2*)(C + (size_t)(r0 + 8) * N + c0) = make_float2(acc[mi][ni][2], acc[mi][ni][3]);
        }
    }
}

__global__ void __launch_bounds__(256, 2) gemm_qkv(const float* __restrict__ A,
        const float* __restrict__ Bq, const float* __restrict__ Bk,
        const float* __restrict__ Bv) {
    extern __shared__ float smf[];
    const int bx = blockIdx.x;
    const float* Bm; float* Cm; int N, bn;
    if (bx < 16)      { Bm = Bq; Cm = g_q; N = 2048; bn = bx * 128; }
    else if (bx < 20) { Bm = Bk; Cm = g_k; N = 512;  bn = (bx - 16) * 128; }
    else              { Bm = Bv; Cm = g_v; N = 512;  bn = (bx - 20) * 128; }
    gemm_core(A, Bm, Cm, N, blockIdx.y * BM, bn, smf, smf + 3 * STG_A);
}

__global__ void __launch_bounds__(256, 2) gemm_wo(const float* __restrict__ A,
        const float* __restrict__ B, float* __restrict__ C) {
    extern __shared__ float smf[];
    gemm_core(A, B, C, HID_, blockIdx.y * BM, blockIdx.x * BN, smf, smf + 3 * STG_A);
}

// ---------------- gate projection (exact fp32) ----------------
__global__ void gate_proj(const float* __restrict__ hs, const float* __restrict__ Wg) {
    const int s = blockIdx.x;
    const int w = threadIdx.x >> 5, l = threadIdx.x & 31;
    const float* row = hs + (size_t)s * HID_;
    float acc = 0.f;
    for (int k = l; k < HID_; k += 32)
        acc = fmaf(row[k], Wg[k * HKV_ + w], acc);
    #pragma unroll
    for (int o = 16; o > 0; o >>= 1)
        acc += __shfl_down_sync(0xffffffffu, acc, o);
    if (l == 0) g_g[s * HKV_ + w] = acc;
}

// ---------------- log-sigmoid + parallel cumsum ----------------
__global__ void gcumsum_kernel() {
    __shared__ float ps[256];
    const int kv = blockIdx.x;
    const int t = threadIdx.x;
    float loc[8]; float s = 0.f;
    #pragma unroll
    for (int i = 0; i < 8; i++) {
        const float x = g_g[(t * 8 + i) * HKV_ + kv];
        const float ls = (x > 0.f) ? -log1pf(__expf(-x)) : x - log1pf(__expf(x));
        loc[i] = ls; s += ls;
    }
    ps[t] = s; __syncthreads();
    for (int o = 1; o < 256; o <<= 1) {
        const float v = (t >= o) ? ps[t - o] : 0.f;
        __syncthreads();
        ps[t] += v;
        __syncthreads();
    }
    float run = (t > 0) ? ps[t - 1] : 0.f;
    #pragma unroll
    for (int i = 0; i < 8; i++) {
        run += loc[i];
        g_gc[kv * S_ + t * 8 + i] = run;
    }
}

// ---------------- RoPE (in place) ----------------
__global__ void rope_kernel(float* __restrict__ x, const float* __restrict__ cosb,
                            const float* __restrict__ sinb, int nheads) {
    const int idx = blockIdx.x * blockDim.x + threadIdx.x;
    const int total = S_ * nheads * 64;
    if (idx >= total) return;
    const int d = idx % 64;
    const int h = (idx / 64) % nheads;
    const int s = idx / (64 * nheads);
    const float c  = cosb[s * 128 + d];
    const float sn = sinb[s * 128 + d];
    float* row = x + (size_t)s * nheads * 128 + h * 128;
    const float x0 = row[d], x1 = row[d + 64];
    row[d]      = x0 * c - x1 * sn;
    row[d + 64] = x1 * c + x0 * sn;
}

// ---------------- tensor-core causal power attention (3xTF32) ----------------
// 64 q-rows x one head per CTA, 8 warps. QK^T and S@V each done with the
// hi/lo split (hi*hi + hi*lo + lo*hi) -> fp32-level accuracy on tensor cores.
// Pitches: PQK=132 (%32==4, row-indexed frags conflict-free),
//          PV=136 (%32==8, col-indexed frags conflict-free), PS=68 (%32==4).
#define PQK 132
#define PV  136
#define PS  68
#define ATTN_SMEM ((2*64*PQK + 64*PV + 64*PS + 3*64) * 4)

__global__ void __launch_bounds__(256) attn_kernel() {
    extern __shared__ float sm[];
    float* Qs  = sm;                    // 64*PQK
    float* Ks  = Qs + 64 * PQK;         // 64*PQK
    float* Vs  = Ks + 64 * PQK;         // 64*PV
    float* Ss  = Vs + 64 * PV;          // 64*PS
    float* Gq  = Ss + 64 * PS;
    float* Gk  = Gq + 64;
    float* den = Gk + 64;

    const int qb = gridDim.x - 1 - blockIdx.x;   // big tiles first
    const int h = blockIdx.y, kv = h / GROUPS_;
    const int tid  = threadIdx.x;
    const int lane = tid & 31, warp = tid >> 5;
    const int ly = lane >> 2, lx = lane & 3;
    const int wm  = (warp & 3) * 16;     // row range (both phases)
    const int wn  = (warp >> 2) * 32;    // QK col range
    const int wn2 = (warp >> 2) * 64;    // SV dim range

    #pragma unroll
    for (int j = 0; j < 8; j++) {
        const int idx = j * 256 + tid;
        const int r = idx >> 5, d = (idx & 31) * 4;
        *(float4*)(Qs + r * PQK + d) =
            *(const float4*)(g_q + (size_t)(qb * 64 + r) * (H_ * D_) + h * D_ + d);
    }
    if (tid < 64) { Gq[tid] = g_gc[kv * S_ + qb * 64 + tid]; den[tid] = 0.f; }
    __syncthreads();

    const float gq0 = Gq[wm + ly];
    const float gq1 = Gq[wm + ly + 8];
    const float Gq0 = Gq[0];

    float o[8][4];
    #pragma unroll
    for (int ni = 0; ni < 8; ni++)
        #pragma unroll
        for (int r = 0; r < 4; r++) o[ni][r] = 0.f;
    float rs0 = 0.f, rs1 = 0.f;

    for (int kb = qb; kb >= 0; kb--) {
        if (kb < qb && Gq0 - g_gc[kv * S_ + kb * 64 + 63] < DECAY_CUT) break;
        __syncthreads();
        #pragma unroll
        for (int j = 0; j < 8; j++) {
            const int idx = j * 256 + tid;
            const int r = idx >> 5, d = (idx & 31) * 4;
            const size_t gbase = (size_t)(kb * 64 + r) * (HKV_ * D_) + kv * D_ + d;
            *(float4*)(Ks + r * PQK + d) = *(const float4*)(g_k + gbase);
            *(float4*)(Vs + r * PV  + d) = *(const float4*)(g_v + gbase);
        }
        if (tid < 64) Gk[tid] = g_gc[kv * S_ + kb * 64 + tid];
        __syncthreads();

        // ---- S = QK^T (3xTF32 mma) ----
        float c[4][4];
        #pragma unroll
        for (int ni = 0; ni < 4; ni++)
            #pragma unroll
            for (int r = 0; r < 4; r++) c[ni][r] = 0.f;
        #pragma unroll
        for (int ks = 0; ks < 128; ks += 8) {
            unsigned ah[4], al[4];
            const float* Qr = Qs + (wm + ly) * PQK + ks + lx;
            split2(Qr[0],           ah[0], al[0]);
            split2(Qr[8 * PQK],     ah[1], al[1]);
            split2(Qr[4],           ah[2], al[2]);
            split2(Qr[8 * PQK + 4], ah[3], al[3]);
            #pragma unroll
            for (int ni = 0; ni < 4; ni++) {
                unsigned bh[2], bl[2];
                const float* Kr = Ks + (wn + ni * 8 + ly) * PQK + ks + lx;
                split2(Kr[0], bh[0], bl[0]);
                split2(Kr[4], bh[1], bl[1]);
                mma_tf32(c[ni], ah, bh);
                mma_tf32(c[ni], al, bh);
                mma_tf32(c[ni], ah, bl);
            }
        }

        // ---- mask, scale^2, decay; rowsums; stage S to smem ----
        const int rg0 = qb * 64 + wm + ly;
        const int rg1 = rg0 + 8;
        #pragma unroll
        for (int ni = 0; ni < 4; ni++) {
            const int col = wn + ni * 8 + 2 * lx;
            const int cg  = kb * 64 + col;
            const float gk0 = Gk[col], gk1 = Gk[col + 1];
            float t;
            t = c[ni][0] * SCALE_;
            const float v00 = (cg     <= rg0) ? t * t * __expf(gq0 - gk0) : 0.f;
            t = c[ni][1] * SCALE_;
            const float v01 = (cg + 1 <= rg0) ? t * t * __expf(gq0 - gk1) : 0.f;
            t = c[ni][2] * SCALE_;
            const float v10 = (cg     <= rg1) ? t * t * __expf(gq1 - gk0) : 0.f;
            t = c[ni][3] * SCALE_;
            const float v11 = (cg + 1 <= rg1) ? t * t * __expf(gq1 - gk1) : 0.f;
            rs0 += v00 + v01;
            rs1 += v10 + v11;
            *(float2*)(Ss + (wm + ly) * PS + col)     = make_float2(v00, v01);
            *(float2*)(Ss + (wm + ly + 8) * PS + col) = make_float2(v10, v11);
        }
        __syncthreads();

        // ---- O += S @ V (3xTF32 mma) ----
        #pragma unroll
        for (int ks = 0; ks < 64; ks += 8) {
            unsigned ah[4], al[4];
            const float* Sr = Ss + (wm + ly) * PS + ks + lx;
            split2(Sr[0],          ah[0], al[0]);
            split2(Sr[8 * PS],     ah[1], al[1]);
            split2(Sr[4],          ah[2], al[2]);
            split2(Sr[8 * PS + 4], ah[3], al[3]);
            #pragma unroll
            for (int ni = 0; ni < 8; ni++) {
                unsigned bh[2], bl[2];
                const float* Vr = Vs + (ks + lx) * PV + wn2 + ni * 8 + ly;
                split2(Vr[0],      bh[0], bl[0]);
                split2(Vr[4 * PV], bh[1], bl[1]);
                mma_tf32(o[ni], ah, bh);
                mma_tf32(o[ni], al, bh);
                mma_tf32(o[ni], ah, bl);
            }
        }
    }

    rs0 += __shfl_xor_sync(0xffffffffu, rs0, 1);
    rs0 += __shfl_xor_sync(0xffffffffu, rs0, 2);
    rs1 += __shfl_xor_sync(0xffffffffu, rs1, 1);
    rs1 += __shfl_xor_sync(0xffffffffu, rs1, 2);
    if (lx == 0) {
        atomicAdd(&den[wm + ly], rs0);
        atomicAdd(&den[wm + ly + 8], rs1);
    }
    __syncthreads();

    const float inv0 = 1.f / fmaxf(den[wm + ly], 1.f);
    const float inv1 = 1.f / fmaxf(den[wm + ly + 8], 1.f);
    #pragma unroll
    for (int ni = 0; ni < 8; ni++) {
        const int colg = h * D_ + wn2 + ni * 8 + 2 * lx;
        float* d0 = g_attn + (size_t)(qb * 64 + wm + ly) * (H_ * D_) + colg;
        float* d1 = g_attn + (size_t)(qb * 64 + wm + ly + 8) * (H_ * D_) + colg;
        *(float2*)d0 = make_float2(o[ni][0] * inv0, o[ni][1] * inv0);
        *(float2*)d1 = make_float2(o[ni][2] * inv1, o[ni][3] * inv1);
    }
}

// ---------------- launch ----------------
extern "C" void kernel_launch(void* const* d_in, const int* in_sizes, int n_in,
                              void* d_out, int out_size) {
    (void)in_sizes; (void)n_in; (void)out_size;
    const float* hs   = (const float*)d_in[0];
    const float* cosb = (const float*)d_in[1];
    const float* sinb = (const float*)d_in[2];
    const float* Wq   = (const float*)d_in[3];
    const float* Wk   = (const float*)d_in[4];
    const float* Wv   = (const float*)d_in[5];
    const float* Wg   = (const float*)d_in[6];
    const float* Wo   = (const float*)d_in[7];
    float* out = (float*)d_out;

    float *q, *k, *attn, *hsr, *wqr, *wkr, *wvr, *wor;
    cudaGetSymbolAddress((void**)&q,    g_q);
    cudaGetSymbolAddress((void**)&k,    g_k);
    cudaGetSymbolAddress((void**)&attn, g_attn);
    cudaGetSymbolAddress((void**)&hsr,  g_hsr);
    cudaGetSymbolAddress((void**)&wqr,  g_wqr);
    cudaGetSymbolAddress((void**)&wkr,  g_wkr);
    cudaGetSymbolAddress((void**)&wvr,  g_wvr);
    cudaGetSymbolAddress((void**)&wor,  g_wor);

    static cudaStream_t s1 = nullptr, s2 = nullptr;
    static cudaEvent_t ev0, ev1, ev2, ev2a;
    if (!s1) {
        cudaStreamCreateWithFlags(&s1, cudaStreamNonBlocking);
        cudaStreamCreateWithFlags(&s2, cudaStreamNonBlocking);
        cudaEventCreateWithFlags(&ev0,  cudaEventDisableTiming);
        cudaEventCreateWithFlags(&ev1,  cudaEventDisableTiming);
        cudaEventCreateWithFlags(&ev2,  cudaEventDisableTiming);
        cudaEventCreateWithFlags(&ev2a, cudaEventDisableTiming);
    }

    cudaFuncSetAttribute(gemm_qkv, cudaFuncAttributeMaxDynamicSharedMemorySize, GEMM_SMEM3);
    cudaFuncSetAttribute(gemm_wo,  cudaFuncAttributeMaxDynamicSharedMemorySize, GEMM_SMEM3);
    cudaFuncSetAttribute(attn_kernel, cudaFuncAttributeMaxDynamicSharedMemorySize, ATTN_SMEM);

    cudaEventRecord(ev0, 0);

    // side stream 2: weight prerounds
    cudaStreamWaitEvent(s2, ev0, 0);
    preround<<<(HID_*H_*D_)   / 1024, 256, 0, s2>>>(Wq, wqr);
    preround<<<(HID_*HKV_*D_) / 1024, 256, 0, s2>>>(Wk, wkr);
    preround<<<(HID_*HKV_*D_) / 1024, 256, 0, s2>>>(Wv, wvr);
    cudaEventRecord(ev2a, s2);
    preround<<<(H_*D_*HID_)   / 1024, 256, 0, s2>>>(Wo, wor);
    cudaEventRecord(ev2, s2);

    // side stream 1: gate path (exact fp32)
    cudaStreamWaitEvent(s1, ev0, 0);
    gate_proj<<<S_, 128, 0, s1>>>(hs, Wg);
    gcumsum_kernel<<<HKV_, 256, 0, s1>>>();
    cudaEventRecord(ev1, s1);

    // main stream
    preround<<<(S_*HID_) / 1024, 256>>>(hs, hsr);
    cudaStreamWaitEvent(0, ev2a, 0);
    gemm_qkv<<<dim3(24, S_ / BM), 256, GEMM_SMEM3>>>(hsr, wqr, wkr, wvr);
    rope_kernel<<<(S_*H_*64   + 255) / 256, 256>>>(q, cosb, sinb, H_);
    rope_kernel<<<(S_*HKV_*64 + 255) / 256, 256>>>(k, cosb, sinb, HKV_);

    cudaStreamWaitEvent(0, ev1, 0);
    attn_kernel<<<dim3(S_ / 64, H_), 256, ATTN_SMEM>>>();

    cudaStreamWaitEvent(0, ev2, 0);
    gemm_wo<<<dim3(HID_ / BN, S_ / BM), 256, GEMM_SMEM3>>>(attn, wor, out);
}